// round 13
// baseline (speedup 1.0000x reference)
#include <cuda_runtime.h>
#include <cuda_fp16.h>
#include <math.h>
#include <stdint.h>

// Problem constants
#define LL   8
#define DD   512
#define HH   8
#define DHH  64
#define SS   64
#define VV   66
#define BB   256
#define MM   (BB * SS)      // 16384 token rows
#define DFF  (4 * DD)       // 2048
#define KQKV (3 * DD)       // 1536

// ---------------- scratch (static device allocations; no cudaMalloc) -------
__device__ float g_x[(size_t)MM * DD];
__device__ __half g_x16[(size_t)MM * DD];        // fp16 shadow of residual
__device__ float g_h[(size_t)MM * DD];
__device__ __half g_qkv[(size_t)MM * KQKV];      // fp16 qkv [M, 1536]
__device__ __half g_hA1[(size_t)MM * DD];        // single-fp16 LN out
__device__ __half g_oA[(size_t)MM * DD];         // single-fp16 attn out
__device__ __half g_hidA[(size_t)MM * DFF];      // single-fp16 gelu out
__device__ float g_logits[(size_t)MM * VV];
__device__ float g_loss;

// fp16 transposed weights (all single)
__device__ __half g_Wqkv[(size_t)LL * KQKV * DD];   // [1536][512]
__device__ __half g_WoT [(size_t)LL * DD * DD];     // [512][512]
__device__ __half g_W1T [(size_t)LL * DFF * DD];    // [2048][512]
__device__ __half g_W2T [(size_t)LL * DD * DFF];    // [512][2048]

// ============================ PTX helpers ===================================
__device__ __forceinline__ uint32_t smem_u32(const void* p) {
    uint32_t a;
    asm("{ .reg .u64 t; cvta.to.shared.u64 t, %1; cvt.u32.u64 %0, t; }"
        : "=r"(a) : "l"(p));
    return a;
}
__device__ __forceinline__ void cp16(uint32_t s, const void* g) {
    asm volatile("cp.async.cg.shared.global [%0], [%1], 16;" :: "r"(s), "l"(g));
}
__device__ __forceinline__ void cp_commit() {
    asm volatile("cp.async.commit_group;" ::: "memory");
}
template<int N>
__device__ __forceinline__ void cp_wait() {
    asm volatile("cp.async.wait_group %0;" :: "n"(N) : "memory");
}
__device__ __forceinline__ void ldsm4(uint32_t* r, uint32_t addr) {
    asm volatile("ldmatrix.sync.aligned.m8n8.x4.shared.b16 {%0,%1,%2,%3}, [%4];"
        : "=r"(r[0]), "=r"(r[1]), "=r"(r[2]), "=r"(r[3]) : "r"(addr));
}
__device__ __forceinline__ void ldsm4t(uint32_t* r, uint32_t addr) {
    asm volatile("ldmatrix.sync.aligned.m8n8.x4.trans.shared.b16 {%0,%1,%2,%3}, [%4];"
        : "=r"(r[0]), "=r"(r[1]), "=r"(r[2]), "=r"(r[3]) : "r"(addr));
}
__device__ __forceinline__ void mma16816(float* d, const uint32_t* a, uint32_t b0, uint32_t b1) {
    asm volatile(
        "mma.sync.aligned.m16n8k16.row.col.f32.f16.f16.f32 "
        "{%0,%1,%2,%3}, {%4,%5,%6,%7}, {%8,%9}, {%0,%1,%2,%3};"
        : "+f"(d[0]), "+f"(d[1]), "+f"(d[2]), "+f"(d[3])
        : "r"(a[0]), "r"(a[1]), "r"(a[2]), "r"(a[3]), "r"(b0), "r"(b1));
}
__device__ __forceinline__ uint32_t pack_h2(float x, float y) {
    __half2 h = __halves2half2(__float2half_rn(x), __float2half_rn(y));
    return *(uint32_t*)&h;
}

// ============================ HMMA GEMM =====================================
// (mainloop unchanged — proven at ~97% of legacy-HMMA ceiling)
// EPI 0: C2 fp16 = acc
// EPI 1: C fp32 = acc + bias + res (res==C ok); ALSO X16 fp16 = same value
// EPI 2: C2 fp16 = gelu(acc + bias)
#define STG       3
#define STG_BYTES 32768u
#define GSMEM     (STG * 32768)

template<int EPI>
__global__ void __launch_bounds__(128, 2)
gemm_mma(const __half* __restrict__ A, int lda,
         const __half* __restrict__ B, int ldb,
         int K3,
         float* __restrict__ C, __half* __restrict__ C2, int ldc,
         const float* __restrict__ bias,
         float* __restrict__ res,
         __half* __restrict__ X16)
{
    extern __shared__ char smem[];
    const int t    = threadIdx.x;
    const int wid  = t >> 5, lane = t & 31;
    const int brow = blockIdx.y * 128;
    const int bcol = blockIdx.x * 128;
    const int wm   = (wid & 1) * 64;
    const int wn   = (wid >> 1) * 64;

    uint32_t sbase = smem_u32(smem);

    float acc[4][8][4];
    #pragma unroll
    for (int i = 0; i < 4; i++)
        #pragma unroll
        for (int j = 0; j < 8; j++)
            #pragma unroll
            for (int e = 0; e < 4; e++) acc[i][j][e] = 0.0f;

    auto load_stage = [&](int s) {
        int buf = s % STG;
        int k0  = s << 6;
        uint32_t sa = sbase + buf * STG_BYTES;
        uint32_t sb = sa + 16384u;
        #pragma unroll
        for (int i = 0; i < 8; i++) {
            int c   = t + (i << 7);
            int row = c >> 3;
            int c16 = c & 7;
            uint32_t off = (uint32_t)(row * 128 + c16 * 16);
            off ^= (off >> 3) & 0x70u;
            cp16(sa + off, A + (size_t)(brow + row) * lda + k0 + c16 * 8);
        }
        #pragma unroll
        for (int i = 0; i < 8; i++) {
            int c   = t + (i << 7);
            int row = c >> 3;
            int c16 = c & 7;
            uint32_t off = (uint32_t)(row * 128 + c16 * 16);
            off ^= (off >> 3) & 0x70u;
            cp16(sb + off, B + (size_t)(bcol + row) * ldb + k0 + c16 * 8);
        }
        cp_commit();
    };

    const int S = K3 >> 6;

    const int lrow = ((lane >> 3) & 1) * 8 + (lane & 7);
    const int lkb  = (lane >> 4) * 16;

    load_stage(0);
    load_stage(1);

    for (int s = 0; s < S; s++) {
        int buf = s % STG;
        cp_wait<1>();
        __syncthreads();

        uint32_t sa = sbase + buf * STG_BYTES;
        uint32_t sb = sa + 16384u;

        #pragma unroll
        for (int kk = 0; kk < 4; kk++) {
            int kbyte = kk * 32 + lkb;

            uint32_t afr[4][4];
            #pragma unroll
            for (int mi = 0; mi < 4; mi++) {
                uint32_t off = (uint32_t)((wm + mi * 16 + lrow) * 128 + kbyte);
                off ^= (off >> 3) & 0x70u;
                ldsm4(afr[mi], sa + off);
            }
            uint32_t bfr[4][4];
            #pragma unroll
            for (int nj = 0; nj < 4; nj++) {
                uint32_t off = (uint32_t)((wn + nj * 16 + lrow) * 128 + kbyte);
                off ^= (off >> 3) & 0x70u;
                ldsm4(bfr[nj], sb + off);
            }
            #pragma unroll
            for (int mi = 0; mi < 4; mi++) {
                #pragma unroll
                for (int nj = 0; nj < 4; nj++) {
                    mma16816(acc[mi][2 * nj],     afr[mi], bfr[nj][0], bfr[nj][2]);
                    mma16816(acc[mi][2 * nj + 1], afr[mi], bfr[nj][1], bfr[nj][3]);
                }
            }
        }
        __syncthreads();
        if (s + 2 < S) load_stage(s + 2);
    }

    #pragma unroll
    for (int mi = 0; mi < 4; mi++) {
        #pragma unroll
        for (int ni = 0; ni < 8; ni++) {
            int r0 = brow + wm + mi * 16 + (lane >> 2);
            int c0 = bcol + wn + ni * 8 + ((lane & 3) << 1);
            #pragma unroll
            for (int half = 0; half < 2; half++) {
                int row = r0 + half * 8;
                float v0 = acc[mi][ni][half * 2];
                float v1 = acc[mi][ni][half * 2 + 1];
                if (EPI == 0) {
                    *(uint32_t*)&C2[(size_t)row * ldc + c0] = pack_h2(v0, v1);
                } else if (EPI == 1) {
                    float2 bv = *(const float2*)&bias[c0];
                    float2 r  = *(const float2*)&res[(size_t)row * ldc + c0];
                    float o0 = v0 + bv.x + r.x;
                    float o1 = v1 + bv.y + r.y;
                    *(float2*)&C[(size_t)row * ldc + c0] = make_float2(o0, o1);
                    *(uint32_t*)&X16[(size_t)row * ldc + c0] = pack_h2(o0, o1);
                } else {
                    float2 bv = *(const float2*)&bias[c0];
                    float a0 = v0 + bv.x;
                    float a1 = v1 + bv.y;
                    float g0 = 0.5f * a0 * (1.0f + erff(a0 * 0.70710678118654752f));
                    float g1 = 0.5f * a1 * (1.0f + erff(a1 * 0.70710678118654752f));
                    *(uint32_t*)&C2[(size_t)row * ldc + c0] = pack_h2(g0, g1);
                }
            }
        }
    }
}

// ============================ weight prep ===================================
__device__ __forceinline__ void prep_body(
    const float* __restrict__ Wl, int K, int N, __half* __restrict__ ol,
    int k0, int n0, int tx, int ty)
{
    __shared__ float ts[32][33];
    #pragma unroll
    for (int i = 0; i < 32; i += 8)
        ts[ty + i][tx] = Wl[(size_t)(k0 + ty + i) * N + n0 + tx];
    __syncthreads();
    #pragma unroll
    for (int i = 0; i < 32; i += 8) {
        int n = n0 + ty + i, k = k0 + tx;
        ol[(size_t)n * K + k] = __float2half_rn(ts[tx][ty + i]);
    }
}

__global__ void __launch_bounds__(256) prep_w_qkvo(
    const float* __restrict__ Wq, const float* __restrict__ Wk,
    const float* __restrict__ Wv, const float* __restrict__ Wo,
    __half* __restrict__ Wqkv, __half* __restrict__ WoT)
{
    int z = blockIdx.z;
    int l = z >> 2, part = z & 3;
    const float* W = (part == 0) ? Wq : (part == 1) ? Wk : (part == 2) ? Wv : Wo;
    const float* Wl = W + (size_t)l * DD * DD;
    __half* ol = (part < 3)
        ? Wqkv + (size_t)l * KQKV * DD + (size_t)part * DD * DD
        : WoT  + (size_t)l * DD * DD;
    prep_body(Wl, DD, DD, ol, blockIdx.x * 32, blockIdx.y * 32,
              threadIdx.x, threadIdx.y);
}

// W1 (z<8) and W2 (z>=8) merged; grid (64, 16, 16)
__global__ void __launch_bounds__(256) prep_w_mlp(
    const float* __restrict__ W1, const float* __restrict__ W2,
    __half* __restrict__ W1T, __half* __restrict__ W2T)
{
    int z = blockIdx.z;
    int l = z & 7;
    if (z < 8) {
        // W1: K=512 (16 k-tiles via blockIdx.y), N=2048 (64 n-tiles via blockIdx.x)
        prep_body(W1 + (size_t)l * DD * DFF, DD, DFF,
                  W1T + (size_t)l * DFF * DD,
                  blockIdx.y * 32, blockIdx.x * 32, threadIdx.x, threadIdx.y);
    } else {
        // W2: K=2048 (64 k-tiles via blockIdx.x), N=512 (16 n-tiles via blockIdx.y)
        prep_body(W2 + (size_t)l * DFF * DD, DFF, DD,
                  W2T + (size_t)l * DD * DFF,
                  blockIdx.x * 32, blockIdx.y * 32, threadIdx.x, threadIdx.y);
    }
}

// ---------------- embedding (float4) + fp16 shadow + loss reset --------------
__global__ void __launch_bounds__(256) embed_kernel(
    const int* __restrict__ ids, const float* __restrict__ tok,
    const float* __restrict__ pos, float* __restrict__ x,
    __half* __restrict__ x16)
{
    int i = blockIdx.x * 256 + threadIdx.x;      // float4 index, MM*DD/4 total
    if (i == 0) g_loss = 0.0f;
    int row = i >> 7;
    int d4  = i & 127;
    int s   = row & (SS - 1);
    float4 tv = ((const float4*)tok)[(size_t)ids[row] * 128 + d4];
    float4 pv = ((const float4*)pos)[(size_t)s * 128 + d4];
    float4 o = make_float4(tv.x + pv.x, tv.y + pv.y, tv.z + pv.z, tv.w + pv.w);
    ((float4*)x)[i] = o;
    uint2 h;
    h.x = pack_h2(o.x, o.y);
    h.y = pack_h2(o.z, o.w);
    ((uint2*)x16)[i] = h;
}

// ---------------- LayerNorm: warp-per-row (unbiased std, eps on std) --------
__device__ __forceinline__ void ln_warp_stats(const float4* v, float& mean, float& inv)
{
    float s = 0.0f, ss = 0.0f;
    #pragma unroll
    for (int j = 0; j < 4; j++) {
        s  += v[j].x + v[j].y + v[j].z + v[j].w;
        ss += v[j].x * v[j].x + v[j].y * v[j].y + v[j].z * v[j].z + v[j].w * v[j].w;
    }
    #pragma unroll
    for (int o = 16; o; o >>= 1) {
        s  += __shfl_xor_sync(0xffffffffu, s,  o);
        ss += __shfl_xor_sync(0xffffffffu, ss, o);
    }
    mean = s * (1.0f / DD);
    float var = (ss - s * mean) * (1.0f / (DD - 1));
    inv = 1.0f / (sqrtf(fmaxf(var, 0.0f)) + 1e-10f);
}

// fp32 output (final LN) — reads fp32 x to protect logits accuracy
__global__ void __launch_bounds__(256) ln_kernel(
    const float* __restrict__ x, const float* __restrict__ g,
    const float* __restrict__ b, float* __restrict__ out)
{
    int warp = threadIdx.x >> 5, lane = threadIdx.x & 31;
    int row  = blockIdx.x * 8 + warp;
    const float4* xr = (const float4*)(x + (size_t)row * DD);
    const float4* gr = (const float4*)g;
    const float4* br = (const float4*)b;
    float4 v[4];
    #pragma unroll
    for (int j = 0; j < 4; j++) v[j] = xr[lane + 32 * j];
    float mean, inv;
    ln_warp_stats(v, mean, inv);
    float4* orow = (float4*)(out + (size_t)row * DD);
    #pragma unroll
    for (int j = 0; j < 4; j++) {
        float4 gv = gr[lane + 32 * j], bv = br[lane + 32 * j];
        float4 ov;
        ov.x = (v[j].x - mean) * inv * gv.x + bv.x;
        ov.y = (v[j].y - mean) * inv * gv.y + bv.y;
        ov.z = (v[j].z - mean) * inv * gv.z + bv.z;
        ov.w = (v[j].w - mean) * inv * gv.w + bv.w;
        orow[lane + 32 * j] = ov;
    }
}

// fp16 output (layer LNs) — reads fp16 x16 shadow (half the DRAM read)
__global__ void __launch_bounds__(256) ln_single_kernel(
    const __half* __restrict__ x16, const float* __restrict__ g,
    const float* __restrict__ b, __half* __restrict__ out)
{
    int warp = threadIdx.x >> 5, lane = threadIdx.x & 31;
    int row  = blockIdx.x * 8 + warp;
    const uint2* xr = (const uint2*)(x16 + (size_t)row * DD);
    const float4* gr = (const float4*)g;
    const float4* br = (const float4*)b;
    float4 v[4];
    #pragma unroll
    for (int j = 0; j < 4; j++) {
        uint2 u = xr[lane + 32 * j];
        float2 lo = __half22float2(*(__half2*)&u.x);
        float2 hi = __half22float2(*(__half2*)&u.y);
        v[j] = make_float4(lo.x, lo.y, hi.x, hi.y);
    }
    float mean, inv;
    ln_warp_stats(v, mean, inv);
    uint2* orow = (uint2*)(out + (size_t)row * DD);
    #pragma unroll
    for (int j = 0; j < 4; j++) {
        float4 gv = gr[lane + 32 * j], bv = br[lane + 32 * j];
        uint2 o;
        o.x = pack_h2((v[j].x - mean) * inv * gv.x + bv.x,
                      (v[j].y - mean) * inv * gv.y + bv.y);
        o.y = pack_h2((v[j].z - mean) * inv * gv.z + bv.z,
                      (v[j].w - mean) * inv * gv.w + bv.w);
        orow[lane + 32 * j] = o;
    }
}

// ---------------- MMA causal attention per (b,h) -----------------------------
__global__ void __launch_bounds__(128) attn_mma_kernel(
    const __half* __restrict__ qkv, __half* __restrict__ oA)
{
    __shared__ __align__(16) char smem[3 * 8192];  // q,k,v tiles 64x128B SW128

    int bh = blockIdx.x;
    int b  = bh >> 3;
    int h  = bh & 7;
    const __half* qb = qkv + (size_t)b * SS * KQKV + h * DHH;
    const __half* kb = qb + DD;
    const __half* vb = qb + 2 * DD;
    __half* ob = oA + (size_t)b * SS * DD + h * DHH;

    uint32_t sq = smem_u32(smem);
    uint32_t sk = sq + 8192u;
    uint32_t sv = sq + 16384u;

    int t = threadIdx.x, wid = t >> 5, lane = t & 31;

    for (int i = t; i < 512; i += 128) {
        int row = i >> 3, c = i & 7;
        uint32_t off = (uint32_t)(row * 128 + c * 16);
        off ^= (off >> 3) & 0x70u;
        const size_t go = (size_t)row * KQKV + c * 8;
        cp16(sq + off, qb + go);
        cp16(sk + off, kb + go);
        cp16(sv + off, vb + go);
    }
    cp_commit();
    cp_wait<0>();
    __syncthreads();

    const int m0   = wid * 16;
    const int lrow = ((lane >> 3) & 1) * 8 + (lane & 7);
    const int lkb  = (lane >> 4) * 16;

    float sc[8][4];
    #pragma unroll
    for (int i = 0; i < 8; i++)
        #pragma unroll
        for (int e = 0; e < 4; e++) sc[i][e] = 0.0f;

    #pragma unroll
    for (int kk = 0; kk < 4; kk++) {
        int kbyte = kk * 32 + lkb;
        uint32_t aoff = (uint32_t)((m0 + lrow) * 128 + kbyte);
        aoff ^= (aoff >> 3) & 0x70u;
        uint32_t afr[4];
        ldsm4(afr, sq + aoff);
        #pragma unroll
        for (int nj = 0; nj < 4; nj++) {
            uint32_t boff = (uint32_t)((nj * 16 + lrow) * 128 + kbyte);
            boff ^= (boff >> 3) & 0x70u;
            uint32_t bfr[4];
            ldsm4(bfr, sk + boff);
            mma16816(sc[2 * nj],     afr, bfr[0], bfr[2]);
            mma16816(sc[2 * nj + 1], afr, bfr[1], bfr[3]);
        }
    }

    const float scale = 0.044194173824159216f;  // 1/sqrt(512)
    int r_lo = m0 + (lane >> 2);
    int r_hi = r_lo + 8;
    float mx0 = -1e30f, mx1 = -1e30f;
    #pragma unroll
    for (int nt = 0; nt < 8; nt++) {
        int c0 = nt * 8 + ((lane & 3) << 1);
        sc[nt][0] = (c0     <= r_lo) ? sc[nt][0] * scale : -1e30f;
        sc[nt][1] = (c0 + 1 <= r_lo) ? sc[nt][1] * scale : -1e30f;
        sc[nt][2] = (c0     <= r_hi) ? sc[nt][2] * scale : -1e30f;
        sc[nt][3] = (c0 + 1 <= r_hi) ? sc[nt][3] * scale : -1e30f;
        mx0 = fmaxf(mx0, fmaxf(sc[nt][0], sc[nt][1]));
        mx1 = fmaxf(mx1, fmaxf(sc[nt][2], sc[nt][3]));
    }
    mx0 = fmaxf(mx0, __shfl_xor_sync(0xffffffffu, mx0, 1));
    mx0 = fmaxf(mx0, __shfl_xor_sync(0xffffffffu, mx0, 2));
    mx1 = fmaxf(mx1, __shfl_xor_sync(0xffffffffu, mx1, 1));
    mx1 = fmaxf(mx1, __shfl_xor_sync(0xffffffffu, mx1, 2));

    float sum0 = 0.0f, sum1 = 0.0f;
    #pragma unroll
    for (int nt = 0; nt < 8; nt++) {
        sc[nt][0] = __expf(sc[nt][0] - mx0);
        sc[nt][1] = __expf(sc[nt][1] - mx0);
        sc[nt][2] = __expf(sc[nt][2] - mx1);
        sc[nt][3] = __expf(sc[nt][3] - mx1);
        sum0 += sc[nt][0] + sc[nt][1];
        sum1 += sc[nt][2] + sc[nt][3];
    }
    sum0 += __shfl_xor_sync(0xffffffffu, sum0, 1);
    sum0 += __shfl_xor_sync(0xffffffffu, sum0, 2);
    sum1 += __shfl_xor_sync(0xffffffffu, sum1, 1);
    sum1 += __shfl_xor_sync(0xffffffffu, sum1, 2);
    float inv0 = 1.0f / sum0, inv1 = 1.0f / sum1;

    float oacc[8][4];
    #pragma unroll
    for (int i = 0; i < 8; i++)
        #pragma unroll
        for (int e = 0; e < 4; e++) oacc[i][e] = 0.0f;

    int jrow = lane & 15;
    int echunk = (lane >> 4) * 16;
    #pragma unroll
    for (int kk = 0; kk < 4; kk++) {
        uint32_t afr[4];
        afr[0] = pack_h2(sc[2 * kk][0] * inv0,     sc[2 * kk][1] * inv0);
        afr[1] = pack_h2(sc[2 * kk][2] * inv1,     sc[2 * kk][3] * inv1);
        afr[2] = pack_h2(sc[2 * kk + 1][0] * inv0, sc[2 * kk + 1][1] * inv0);
        afr[3] = pack_h2(sc[2 * kk + 1][2] * inv1, sc[2 * kk + 1][3] * inv1);

        #pragma unroll
        for (int ne = 0; ne < 4; ne++) {
            uint32_t boff = (uint32_t)((kk * 16 + jrow) * 128 + ne * 32 + echunk);
            boff ^= (boff >> 3) & 0x70u;
            uint32_t bfr[4];
            ldsm4t(bfr, sv + boff);
            mma16816(oacc[2 * ne],     afr, bfr[0], bfr[1]);
            mma16816(oacc[2 * ne + 1], afr, bfr[2], bfr[3]);
        }
    }

    #pragma unroll
    for (int nt = 0; nt < 8; nt++) {
        int e = nt * 8 + ((lane & 3) << 1);
        *(uint32_t*)&ob[(size_t)r_lo * DD + e] = pack_h2(oacc[nt][0], oacc[nt][1]);
        *(uint32_t*)&ob[(size_t)r_hi * DD + e] = pack_h2(oacc[nt][2], oacc[nt][3]);
    }
}

// ---------------- fused unembed + cross-entropy loss ------------------------
#define UROWS 16
__global__ void __launch_bounds__(128) unembed_loss_kernel(
    const float* __restrict__ x, const float* __restrict__ Wu,
    const float* __restrict__ bu, const int* __restrict__ tgt,
    float* __restrict__ logits)
{
    __shared__ float xs[UROWS][DD];
    __shared__ float lgs[UROWS][VV + 2];
    int r0 = blockIdx.x * UROWS;
    const float4* src = (const float4*)(x + (size_t)r0 * DD);
    float4* dst = (float4*)&xs[0][0];
    for (int i = threadIdx.x; i < UROWS * DD / 4; i += 128)
        dst[i] = src[i];
    __syncthreads();
    int c = threadIdx.x;
    if (c < VV) {
        float acc[UROWS];
        float bc = bu[c];
        #pragma unroll
        for (int r = 0; r < UROWS; r++) acc[r] = bc;
        #pragma unroll 4
        for (int k = 0; k < DD; k++) {
            float w = Wu[(size_t)k * VV + c];
            #pragma unroll
            for (int r = 0; r < UROWS; r++)
                acc[r] = fmaf(xs[r][k], w, acc[r]);
        }
        #pragma unroll
        for (int r = 0; r < UROWS; r++) {
            logits[(size_t)(r0 + r) * VV + c] = acc[r];
            lgs[r][c] = acc[r];
        }
    }
    __syncthreads();

    int wid = threadIdx.x >> 5, lane = threadIdx.x & 31;
    float part = 0.0f;
    #pragma unroll
    for (int rr = 0; rr < 4; rr++) {
        int r = wid * 4 + rr;
        float l0 = lgs[r][lane];
        float l1 = lgs[r][lane + 32];
        float l2 = (lane + 64 < VV) ? lgs[r][lane + 64] : -1e30f;
        float m = fmaxf(fmaxf(l0, l1), l2);
        #pragma unroll
        for (int off = 16; off; off >>= 1)
            m = fmaxf(m, __shfl_xor_sync(0xffffffffu, m, off));
        float sum = expf(l0 - m) + expf(l1 - m) +
                    ((lane + 64 < VV) ? expf(l2 - m) : 0.0f);
        #pragma unroll
        for (int off = 16; off; off >>= 1)
            sum += __shfl_xor_sync(0xffffffffu, sum, off);
        if (lane == 0)
            part += (m + logf(sum)) - lgs[r][tgt[r0 + r]];
    }
    if (lane == 0) atomicAdd(&g_loss, part);
}

// ---------------- output assembly -------------------------------------------
__global__ void __launch_bounds__(256) copy_out_kernel(
    const float* __restrict__ lg, float* __restrict__ out, int n)
{
    int i = blockIdx.x * 256 + threadIdx.x;
    if (i < n) out[i] = lg[i];
}
__global__ void __launch_bounds__(128) write_loss_kernel(
    float* __restrict__ out, int lo, int hi)
{
    int i = lo + blockIdx.x * 128 + threadIdx.x;
    if (i < hi) out[i] = g_loss * (1.0f / (float)MM);
}

// ---------------- launcher ----------------------------------------------------
extern "C" void kernel_launch(void* const* d_in, const int* in_sizes, int n_in,
                              void* d_out, int out_size)
{
    const int*   ids  = (const int*)d_in[0];
    const int*   tgt  = (const int*)d_in[1];
    const float* tok  = (const float*)d_in[2];
    const float* pos  = (const float*)d_in[3];
    const float* Wq   = (const float*)d_in[4];
    const float* Wk   = (const float*)d_in[5];
    const float* Wv   = (const float*)d_in[6];
    const float* Wo   = (const float*)d_in[7];
    const float* bo   = (const float*)d_in[8];
    const float* W1   = (const float*)d_in[9];
    const float* b1   = (const float*)d_in[10];
    const float* W2   = (const float*)d_in[11];
    const float* b2   = (const float*)d_in[12];
    const float* ln1g = (const float*)d_in[13];
    const float* ln1b = (const float*)d_in[14];
    const float* ln2g = (const float*)d_in[15];
    const float* ln2b = (const float*)d_in[16];
    const float* lnfg = (const float*)d_in[17];
    const float* lnfb = (const float*)d_in[18];
    const float* Wu   = (const float*)d_in[19];
    const float* bu   = (const float*)d_in[20];
    float* out = (float*)d_out;

    float *x, *h, *lg;
    __half *x16, *qkv, *hA1, *oA, *hidA, *Wqkv, *WoT, *W1T, *W2T;
    cudaGetSymbolAddress((void**)&x,    g_x);
    cudaGetSymbolAddress((void**)&x16,  g_x16);
    cudaGetSymbolAddress((void**)&h,    g_h);
    cudaGetSymbolAddress((void**)&qkv,  g_qkv);
    cudaGetSymbolAddress((void**)&hA1,  g_hA1);
    cudaGetSymbolAddress((void**)&oA,   g_oA);
    cudaGetSymbolAddress((void**)&hidA, g_hidA);
    cudaGetSymbolAddress((void**)&lg,   g_logits);
    cudaGetSymbolAddress((void**)&Wqkv, g_Wqkv);
    cudaGetSymbolAddress((void**)&WoT,  g_WoT);
    cudaGetSymbolAddress((void**)&W1T,  g_W1T);
    cudaGetSymbolAddress((void**)&W2T,  g_W2T);

    cudaFuncSetAttribute(gemm_mma<0>, cudaFuncAttributeMaxDynamicSharedMemorySize, GSMEM);
    cudaFuncSetAttribute(gemm_mma<1>, cudaFuncAttributeMaxDynamicSharedMemorySize, GSMEM);
    cudaFuncSetAttribute(gemm_mma<2>, cudaFuncAttributeMaxDynamicSharedMemorySize, GSMEM);

    int nlog = MM * VV;
    float* logits_dst = (out_size >= nlog) ? out : lg;

    // ---- weight prep: 2 launches ----
    dim3 pb(32, 8);
    prep_w_qkvo<<<dim3(DD/32, DD/32, 4*LL), pb>>>(Wq, Wk, Wv, Wo, Wqkv, WoT);
    prep_w_mlp<<<dim3(64, 16, 2*LL), pb>>>(W1, W2, W1T, W2T);

    embed_kernel<<<(MM * DD / 4) / 256, 256>>>(ids, tok, pos, x, x16);

    for (int l = 0; l < LL; l++) {
        ln_single_kernel<<<MM / 8, 256>>>(x16, ln1g + l * DD, ln1b + l * DD, hA1);

        // qkv(fp16) = hA1 @ Wqkv^T   K=512
        gemm_mma<0><<<dim3(KQKV/128, MM/128), 128, GSMEM>>>(
            hA1, DD, Wqkv + (size_t)l*KQKV*DD, DD, DD,
            nullptr, qkv, KQKV, nullptr, nullptr, nullptr);

        attn_mma_kernel<<<BB * HH, 128>>>(qkv, oA);

        // x = x + o @ Wo + bo  (+ x16 shadow)   K=512
        gemm_mma<1><<<dim3(DD/128, MM/128), 128, GSMEM>>>(
            oA, DD, WoT + (size_t)l*DD*DD, DD, DD,
            x, nullptr, DD, bo + l * DD, x, x16);

        ln_single_kernel<<<MM / 8, 256>>>(x16, ln2g + l * DD, ln2b + l * DD, hA1);

        // hidA(fp16) = gelu(hA1 @ W1^T + b1)   K=512
        gemm_mma<2><<<dim3(DFF/128, MM/128), 128, GSMEM>>>(
            hA1, DD, W1T + (size_t)l*DFF*DD, DD, DD,
            nullptr, hidA, DFF, b1 + l * DFF, nullptr, nullptr);

        // x = x + hid @ W2 + b2  (+ x16 shadow)   K=2048
        gemm_mma<1><<<dim3(DD/128, MM/128), 128, GSMEM>>>(
            hidA, DFF, W2T + (size_t)l*DD*DFF, DFF, DFF,
            x, nullptr, DD, b2 + l * DD, x, x16);
    }

    ln_kernel<<<MM / 8, 256>>>(x, lnfg, lnfb, h);
    unembed_loss_kernel<<<MM / UROWS, 128>>>(h, Wu, bu, tgt, logits_dst);

    if (logits_dst != out) {
        int ncopy = out_size < nlog ? out_size : nlog;
        if (ncopy > 0)
            copy_out_kernel<<<(ncopy + 255) / 256, 256>>>(lg, out, ncopy);
    }
    if (out_size > nlog) {
        int tail = out_size - nlog;
        write_loss_kernel<<<(tail + 127) / 128, 128>>>(out, nlog, out_size);
    }
}

// round 14
// speedup vs baseline: 1.0274x; 1.0274x over previous
#include <cuda_runtime.h>
#include <cuda_fp16.h>
#include <math.h>
#include <stdint.h>

// Problem constants
#define LL   8
#define DD   512
#define HH   8
#define DHH  64
#define SS   64
#define VV   66
#define BB   256
#define MM   (BB * SS)      // 16384 token rows
#define DFF  (4 * DD)       // 2048
#define KQKV (3 * DD)       // 1536

// ---------------- scratch (static device allocations; no cudaMalloc) -------
__device__ float g_x[(size_t)MM * DD];
__device__ float g_h[(size_t)MM * DD];
__device__ __half g_qkv[(size_t)MM * KQKV];      // fp16 qkv [M, 1536]
__device__ __half g_hA1[(size_t)MM * DD];        // single-fp16 LN out
__device__ __half g_oA[(size_t)MM * DD];         // single-fp16 attn out
__device__ __half g_hidA[(size_t)MM * DFF];      // single-fp16 gelu out
__device__ float g_logits[(size_t)MM * VV];
__device__ float g_loss;

// fp16 transposed weights (all single)
__device__ __half g_Wqkv[(size_t)LL * KQKV * DD];   // [1536][512]
__device__ __half g_WoT [(size_t)LL * DD * DD];     // [512][512]
__device__ __half g_W1T [(size_t)LL * DFF * DD];    // [2048][512]
__device__ __half g_W2T [(size_t)LL * DD * DFF];    // [512][2048]

// ============================ PTX helpers ===================================
__device__ __forceinline__ uint32_t smem_u32(const void* p) {
    uint32_t a;
    asm("{ .reg .u64 t; cvta.to.shared.u64 t, %1; cvt.u32.u64 %0, t; }"
        : "=r"(a) : "l"(p));
    return a;
}
__device__ __forceinline__ void cp16(uint32_t s, const void* g) {
    asm volatile("cp.async.cg.shared.global [%0], [%1], 16;" :: "r"(s), "l"(g));
}
__device__ __forceinline__ void cp_commit() {
    asm volatile("cp.async.commit_group;" ::: "memory");
}
template<int N>
__device__ __forceinline__ void cp_wait() {
    asm volatile("cp.async.wait_group %0;" :: "n"(N) : "memory");
}
__device__ __forceinline__ void ldsm4(uint32_t* r, uint32_t addr) {
    asm volatile("ldmatrix.sync.aligned.m8n8.x4.shared.b16 {%0,%1,%2,%3}, [%4];"
        : "=r"(r[0]), "=r"(r[1]), "=r"(r[2]), "=r"(r[3]) : "r"(addr));
}
__device__ __forceinline__ void ldsm4t(uint32_t* r, uint32_t addr) {
    asm volatile("ldmatrix.sync.aligned.m8n8.x4.trans.shared.b16 {%0,%1,%2,%3}, [%4];"
        : "=r"(r[0]), "=r"(r[1]), "=r"(r[2]), "=r"(r[3]) : "r"(addr));
}
__device__ __forceinline__ void mma16816(float* d, const uint32_t* a, uint32_t b0, uint32_t b1) {
    asm volatile(
        "mma.sync.aligned.m16n8k16.row.col.f32.f16.f16.f32 "
        "{%0,%1,%2,%3}, {%4,%5,%6,%7}, {%8,%9}, {%0,%1,%2,%3};"
        : "+f"(d[0]), "+f"(d[1]), "+f"(d[2]), "+f"(d[3])
        : "r"(a[0]), "r"(a[1]), "r"(a[2]), "r"(a[3]), "r"(b0), "r"(b1));
}
__device__ __forceinline__ uint32_t pack_h2(float x, float y) {
    __half2 h = __halves2half2(__float2half_rn(x), __float2half_rn(y));
    return *(uint32_t*)&h;
}

// ============================ HMMA GEMM =====================================
// (unchanged — proven at ~97% of legacy-HMMA ceiling)
#define STG       3
#define STG_BYTES 32768u
#define GSMEM     (STG * 32768)

template<int EPI>
__global__ void __launch_bounds__(128, 2)
gemm_mma(const __half* __restrict__ A, int lda,
         const __half* __restrict__ B, int ldb,
         int K3,
         float* __restrict__ C, __half* __restrict__ C2, int ldc,
         const float* __restrict__ bias,
         float* __restrict__ res)
{
    extern __shared__ char smem[];
    const int t    = threadIdx.x;
    const int wid  = t >> 5, lane = t & 31;
    const int brow = blockIdx.y * 128;
    const int bcol = blockIdx.x * 128;
    const int wm   = (wid & 1) * 64;
    const int wn   = (wid >> 1) * 64;

    uint32_t sbase = smem_u32(smem);

    float acc[4][8][4];
    #pragma unroll
    for (int i = 0; i < 4; i++)
        #pragma unroll
        for (int j = 0; j < 8; j++)
            #pragma unroll
            for (int e = 0; e < 4; e++) acc[i][j][e] = 0.0f;

    auto load_stage = [&](int s) {
        int buf = s % STG;
        int k0  = s << 6;
        uint32_t sa = sbase + buf * STG_BYTES;
        uint32_t sb = sa + 16384u;
        #pragma unroll
        for (int i = 0; i < 8; i++) {
            int c   = t + (i << 7);
            int row = c >> 3;
            int c16 = c & 7;
            uint32_t off = (uint32_t)(row * 128 + c16 * 16);
            off ^= (off >> 3) & 0x70u;
            cp16(sa + off, A + (size_t)(brow + row) * lda + k0 + c16 * 8);
        }
        #pragma unroll
        for (int i = 0; i < 8; i++) {
            int c   = t + (i << 7);
            int row = c >> 3;
            int c16 = c & 7;
            uint32_t off = (uint32_t)(row * 128 + c16 * 16);
            off ^= (off >> 3) & 0x70u;
            cp16(sb + off, B + (size_t)(bcol + row) * ldb + k0 + c16 * 8);
        }
        cp_commit();
    };

    const int S = K3 >> 6;

    const int lrow = ((lane >> 3) & 1) * 8 + (lane & 7);
    const int lkb  = (lane >> 4) * 16;

    load_stage(0);
    load_stage(1);

    for (int s = 0; s < S; s++) {
        int buf = s % STG;
        cp_wait<1>();
        __syncthreads();

        uint32_t sa = sbase + buf * STG_BYTES;
        uint32_t sb = sa + 16384u;

        #pragma unroll
        for (int kk = 0; kk < 4; kk++) {
            int kbyte = kk * 32 + lkb;

            uint32_t afr[4][4];
            #pragma unroll
            for (int mi = 0; mi < 4; mi++) {
                uint32_t off = (uint32_t)((wm + mi * 16 + lrow) * 128 + kbyte);
                off ^= (off >> 3) & 0x70u;
                ldsm4(afr[mi], sa + off);
            }
            uint32_t bfr[4][4];
            #pragma unroll
            for (int nj = 0; nj < 4; nj++) {
                uint32_t off = (uint32_t)((wn + nj * 16 + lrow) * 128 + kbyte);
                off ^= (off >> 3) & 0x70u;
                ldsm4(bfr[nj], sb + off);
            }
            #pragma unroll
            for (int mi = 0; mi < 4; mi++) {
                #pragma unroll
                for (int nj = 0; nj < 4; nj++) {
                    mma16816(acc[mi][2 * nj],     afr[mi], bfr[nj][0], bfr[nj][2]);
                    mma16816(acc[mi][2 * nj + 1], afr[mi], bfr[nj][1], bfr[nj][3]);
                }
            }
        }
        __syncthreads();
        if (s + 2 < S) load_stage(s + 2);
    }

    #pragma unroll
    for (int mi = 0; mi < 4; mi++) {
        #pragma unroll
        for (int ni = 0; ni < 8; ni++) {
            int r0 = brow + wm + mi * 16 + (lane >> 2);
            int c0 = bcol + wn + ni * 8 + ((lane & 3) << 1);
            #pragma unroll
            for (int half = 0; half < 2; half++) {
                int row = r0 + half * 8;
                float v0 = acc[mi][ni][half * 2];
                float v1 = acc[mi][ni][half * 2 + 1];
                if (EPI == 0) {
                    *(uint32_t*)&C2[(size_t)row * ldc + c0] = pack_h2(v0, v1);
                } else if (EPI == 1) {
                    float2 bv = *(const float2*)&bias[c0];
                    float2 r  = *(const float2*)&res[(size_t)row * ldc + c0];
                    *(float2*)&C[(size_t)row * ldc + c0] =
                        make_float2(v0 + bv.x + r.x, v1 + bv.y + r.y);
                } else {
                    float2 bv = *(const float2*)&bias[c0];
                    float a0 = v0 + bv.x;
                    float a1 = v1 + bv.y;
                    float g0 = 0.5f * a0 * (1.0f + erff(a0 * 0.70710678118654752f));
                    float g1 = 0.5f * a1 * (1.0f + erff(a1 * 0.70710678118654752f));
                    *(uint32_t*)&C2[(size_t)row * ldc + c0] = pack_h2(g0, g1);
                }
            }
        }
    }
}

// ============================ weight prep ===================================
__device__ __forceinline__ void prep_body(
    const float* __restrict__ Wl, int K, int N, __half* __restrict__ ol,
    int k0, int n0, int tx, int ty)
{
    __shared__ float ts[32][33];
    #pragma unroll
    for (int i = 0; i < 32; i += 8)
        ts[ty + i][tx] = Wl[(size_t)(k0 + ty + i) * N + n0 + tx];
    __syncthreads();
    #pragma unroll
    for (int i = 0; i < 32; i += 8) {
        int n = n0 + ty + i, k = k0 + tx;
        ol[(size_t)n * K + k] = __float2half_rn(ts[tx][ty + i]);
    }
}

__global__ void __launch_bounds__(256) prep_w_qkvo(
    const float* __restrict__ Wq, const float* __restrict__ Wk,
    const float* __restrict__ Wv, const float* __restrict__ Wo,
    __half* __restrict__ Wqkv, __half* __restrict__ WoT)
{
    int z = blockIdx.z;
    int l = z >> 2, part = z & 3;
    const float* W = (part == 0) ? Wq : (part == 1) ? Wk : (part == 2) ? Wv : Wo;
    const float* Wl = W + (size_t)l * DD * DD;
    __half* ol = (part < 3)
        ? Wqkv + (size_t)l * KQKV * DD + (size_t)part * DD * DD
        : WoT  + (size_t)l * DD * DD;
    prep_body(Wl, DD, DD, ol, blockIdx.x * 32, blockIdx.y * 32,
              threadIdx.x, threadIdx.y);
}

// W1 (z<8) and W2 (z>=8) merged; grid (64, 16, 16)
__global__ void __launch_bounds__(256) prep_w_mlp(
    const float* __restrict__ W1, const float* __restrict__ W2,
    __half* __restrict__ W1T, __half* __restrict__ W2T)
{
    int z = blockIdx.z;
    int l = z & 7;
    if (z < 8) {
        prep_body(W1 + (size_t)l * DD * DFF, DD, DFF,
                  W1T + (size_t)l * DFF * DD,
                  blockIdx.y * 32, blockIdx.x * 32, threadIdx.x, threadIdx.y);
    } else {
        prep_body(W2 + (size_t)l * DFF * DD, DFF, DD,
                  W2T + (size_t)l * DD * DFF,
                  blockIdx.x * 32, blockIdx.y * 32, threadIdx.x, threadIdx.y);
    }
}

// ---------------- embedding (float4) + loss reset ----------------------------
__global__ void __launch_bounds__(256) embed_kernel(
    const int* __restrict__ ids, const float* __restrict__ tok,
    const float* __restrict__ pos, float* __restrict__ x)
{
    int i = blockIdx.x * 256 + threadIdx.x;      // float4 index, MM*DD/4 total
    if (i == 0) g_loss = 0.0f;
    int row = i >> 7;                             // DD/4 = 128 float4 per row
    int d4  = i & 127;
    int s   = row & (SS - 1);
    float4 tv = ((const float4*)tok)[(size_t)ids[row] * 128 + d4];
    float4 pv = ((const float4*)pos)[(size_t)s * 128 + d4];
    ((float4*)x)[i] = make_float4(tv.x + pv.x, tv.y + pv.y,
                                  tv.z + pv.z, tv.w + pv.w);
}

// ---------------- LayerNorm: warp-per-row (unbiased std, eps on std) --------
__device__ __forceinline__ void ln_warp_stats(const float4* v, float& mean, float& inv)
{
    float s = 0.0f, ss = 0.0f;
    #pragma unroll
    for (int j = 0; j < 4; j++) {
        s  += v[j].x + v[j].y + v[j].z + v[j].w;
        ss += v[j].x * v[j].x + v[j].y * v[j].y + v[j].z * v[j].z + v[j].w * v[j].w;
    }
    #pragma unroll
    for (int o = 16; o; o >>= 1) {
        s  += __shfl_xor_sync(0xffffffffu, s,  o);
        ss += __shfl_xor_sync(0xffffffffu, ss, o);
    }
    mean = s * (1.0f / DD);
    float var = (ss - s * mean) * (1.0f / (DD - 1));
    inv = 1.0f / (sqrtf(fmaxf(var, 0.0f)) + 1e-10f);
}

// fp32 output (final LN)
__global__ void __launch_bounds__(256) ln_kernel(
    const float* __restrict__ x, const float* __restrict__ g,
    const float* __restrict__ b, float* __restrict__ out)
{
    int warp = threadIdx.x >> 5, lane = threadIdx.x & 31;
    int row  = blockIdx.x * 8 + warp;
    const float4* xr = (const float4*)(x + (size_t)row * DD);
    const float4* gr = (const float4*)g;
    const float4* br = (const float4*)b;
    float4 v[4];
    #pragma unroll
    for (int j = 0; j < 4; j++) v[j] = xr[lane + 32 * j];
    float mean, inv;
    ln_warp_stats(v, mean, inv);
    float4* orow = (float4*)(out + (size_t)row * DD);
    #pragma unroll
    for (int j = 0; j < 4; j++) {
        float4 gv = gr[lane + 32 * j], bv = br[lane + 32 * j];
        float4 ov;
        ov.x = (v[j].x - mean) * inv * gv.x + bv.x;
        ov.y = (v[j].y - mean) * inv * gv.y + bv.y;
        ov.z = (v[j].z - mean) * inv * gv.z + bv.z;
        ov.w = (v[j].w - mean) * inv * gv.w + bv.w;
        orow[lane + 32 * j] = ov;
    }
}

// fp16 output (layer LNs)
__global__ void __launch_bounds__(256) ln_single_kernel(
    const float* __restrict__ x, const float* __restrict__ g,
    const float* __restrict__ b, __half* __restrict__ out)
{
    int warp = threadIdx.x >> 5, lane = threadIdx.x & 31;
    int row  = blockIdx.x * 8 + warp;
    const float4* xr = (const float4*)(x + (size_t)row * DD);
    const float4* gr = (const float4*)g;
    const float4* br = (const float4*)b;
    float4 v[4];
    #pragma unroll
    for (int j = 0; j < 4; j++) v[j] = xr[lane + 32 * j];
    float mean, inv;
    ln_warp_stats(v, mean, inv);
    uint2* orow = (uint2*)(out + (size_t)row * DD);
    #pragma unroll
    for (int j = 0; j < 4; j++) {
        float4 gv = gr[lane + 32 * j], bv = br[lane + 32 * j];
        uint2 o;
        o.x = pack_h2((v[j].x - mean) * inv * gv.x + bv.x,
                      (v[j].y - mean) * inv * gv.y + bv.y);
        o.y = pack_h2((v[j].z - mean) * inv * gv.z + bv.z,
                      (v[j].w - mean) * inv * gv.w + bv.w);
        orow[lane + 32 * j] = o;
    }
}

// ---------------- MMA causal attention per (b,h) -----------------------------
__global__ void __launch_bounds__(128) attn_mma_kernel(
    const __half* __restrict__ qkv, __half* __restrict__ oA)
{
    __shared__ __align__(16) char smem[3 * 8192];  // q,k,v tiles 64x128B SW128

    int bh = blockIdx.x;
    int b  = bh >> 3;
    int h  = bh & 7;
    const __half* qb = qkv + (size_t)b * SS * KQKV + h * DHH;
    const __half* kb = qb + DD;
    const __half* vb = qb + 2 * DD;
    __half* ob = oA + (size_t)b * SS * DD + h * DHH;

    uint32_t sq = smem_u32(smem);
    uint32_t sk = sq + 8192u;
    uint32_t sv = sq + 16384u;

    int t = threadIdx.x, wid = t >> 5, lane = t & 31;

    for (int i = t; i < 512; i += 128) {
        int row = i >> 3, c = i & 7;
        uint32_t off = (uint32_t)(row * 128 + c * 16);
        off ^= (off >> 3) & 0x70u;
        const size_t go = (size_t)row * KQKV + c * 8;
        cp16(sq + off, qb + go);
        cp16(sk + off, kb + go);
        cp16(sv + off, vb + go);
    }
    cp_commit();
    cp_wait<0>();
    __syncthreads();

    const int m0   = wid * 16;
    const int lrow = ((lane >> 3) & 1) * 8 + (lane & 7);
    const int lkb  = (lane >> 4) * 16;

    float sc[8][4];
    #pragma unroll
    for (int i = 0; i < 8; i++)
        #pragma unroll
        for (int e = 0; e < 4; e++) sc[i][e] = 0.0f;

    #pragma unroll
    for (int kk = 0; kk < 4; kk++) {
        int kbyte = kk * 32 + lkb;
        uint32_t aoff = (uint32_t)((m0 + lrow) * 128 + kbyte);
        aoff ^= (aoff >> 3) & 0x70u;
        uint32_t afr[4];
        ldsm4(afr, sq + aoff);
        #pragma unroll
        for (int nj = 0; nj < 4; nj++) {
            uint32_t boff = (uint32_t)((nj * 16 + lrow) * 128 + kbyte);
            boff ^= (boff >> 3) & 0x70u;
            uint32_t bfr[4];
            ldsm4(bfr, sk + boff);
            mma16816(sc[2 * nj],     afr, bfr[0], bfr[2]);
            mma16816(sc[2 * nj + 1], afr, bfr[1], bfr[3]);
        }
    }

    const float scale = 0.044194173824159216f;  // 1/sqrt(512)
    int r_lo = m0 + (lane >> 2);
    int r_hi = r_lo + 8;
    float mx0 = -1e30f, mx1 = -1e30f;
    #pragma unroll
    for (int nt = 0; nt < 8; nt++) {
        int c0 = nt * 8 + ((lane & 3) << 1);
        sc[nt][0] = (c0     <= r_lo) ? sc[nt][0] * scale : -1e30f;
        sc[nt][1] = (c0 + 1 <= r_lo) ? sc[nt][1] * scale : -1e30f;
        sc[nt][2] = (c0     <= r_hi) ? sc[nt][2] * scale : -1e30f;
        sc[nt][3] = (c0 + 1 <= r_hi) ? sc[nt][3] * scale : -1e30f;
        mx0 = fmaxf(mx0, fmaxf(sc[nt][0], sc[nt][1]));
        mx1 = fmaxf(mx1, fmaxf(sc[nt][2], sc[nt][3]));
    }
    mx0 = fmaxf(mx0, __shfl_xor_sync(0xffffffffu, mx0, 1));
    mx0 = fmaxf(mx0, __shfl_xor_sync(0xffffffffu, mx0, 2));
    mx1 = fmaxf(mx1, __shfl_xor_sync(0xffffffffu, mx1, 1));
    mx1 = fmaxf(mx1, __shfl_xor_sync(0xffffffffu, mx1, 2));

    float sum0 = 0.0f, sum1 = 0.0f;
    #pragma unroll
    for (int nt = 0; nt < 8; nt++) {
        sc[nt][0] = __expf(sc[nt][0] - mx0);
        sc[nt][1] = __expf(sc[nt][1] - mx0);
        sc[nt][2] = __expf(sc[nt][2] - mx1);
        sc[nt][3] = __expf(sc[nt][3] - mx1);
        sum0 += sc[nt][0] + sc[nt][1];
        sum1 += sc[nt][2] + sc[nt][3];
    }
    sum0 += __shfl_xor_sync(0xffffffffu, sum0, 1);
    sum0 += __shfl_xor_sync(0xffffffffu, sum0, 2);
    sum1 += __shfl_xor_sync(0xffffffffu, sum1, 1);
    sum1 += __shfl_xor_sync(0xffffffffu, sum1, 2);
    float inv0 = 1.0f / sum0, inv1 = 1.0f / sum1;

    float oacc[8][4];
    #pragma unroll
    for (int i = 0; i < 8; i++)
        #pragma unroll
        for (int e = 0; e < 4; e++) oacc[i][e] = 0.0f;

    int jrow = lane & 15;
    int echunk = (lane >> 4) * 16;
    #pragma unroll
    for (int kk = 0; kk < 4; kk++) {
        uint32_t afr[4];
        afr[0] = pack_h2(sc[2 * kk][0] * inv0,     sc[2 * kk][1] * inv0);
        afr[1] = pack_h2(sc[2 * kk][2] * inv1,     sc[2 * kk][3] * inv1);
        afr[2] = pack_h2(sc[2 * kk + 1][0] * inv0, sc[2 * kk + 1][1] * inv0);
        afr[3] = pack_h2(sc[2 * kk + 1][2] * inv1, sc[2 * kk + 1][3] * inv1);

        #pragma unroll
        for (int ne = 0; ne < 4; ne++) {
            uint32_t boff = (uint32_t)((kk * 16 + jrow) * 128 + ne * 32 + echunk);
            boff ^= (boff >> 3) & 0x70u;
            uint32_t bfr[4];
            ldsm4t(bfr, sv + boff);
            mma16816(oacc[2 * ne],     afr, bfr[0], bfr[1]);
            mma16816(oacc[2 * ne + 1], afr, bfr[2], bfr[3]);
        }
    }

    #pragma unroll
    for (int nt = 0; nt < 8; nt++) {
        int e = nt * 8 + ((lane & 3) << 1);
        *(uint32_t*)&ob[(size_t)r_lo * DD + e] = pack_h2(oacc[nt][0], oacc[nt][1]);
        *(uint32_t*)&ob[(size_t)r_hi * DD + e] = pack_h2(oacc[nt][2], oacc[nt][3]);
    }
}

// ---------------- fused unembed + cross-entropy loss ------------------------
#define UROWS 16
__global__ void __launch_bounds__(128) unembed_loss_kernel(
    const float* __restrict__ x, const float* __restrict__ Wu,
    const float* __restrict__ bu, const int* __restrict__ tgt,
    float* __restrict__ logits)
{
    __shared__ float xs[UROWS][DD];
    __shared__ float lgs[UROWS][VV + 2];
    int r0 = blockIdx.x * UROWS;
    const float4* src = (const float4*)(x + (size_t)r0 * DD);
    float4* dst = (float4*)&xs[0][0];
    for (int i = threadIdx.x; i < UROWS * DD / 4; i += 128)
        dst[i] = src[i];
    __syncthreads();
    int c = threadIdx.x;
    if (c < VV) {
        float acc[UROWS];
        float bc = bu[c];
        #pragma unroll
        for (int r = 0; r < UROWS; r++) acc[r] = bc;
        #pragma unroll 4
        for (int k = 0; k < DD; k++) {
            float w = Wu[(size_t)k * VV + c];
            #pragma unroll
            for (int r = 0; r < UROWS; r++)
                acc[r] = fmaf(xs[r][k], w, acc[r]);
        }
        #pragma unroll
        for (int r = 0; r < UROWS; r++) {
            logits[(size_t)(r0 + r) * VV + c] = acc[r];
            lgs[r][c] = acc[r];
        }
    }
    __syncthreads();

    int wid = threadIdx.x >> 5, lane = threadIdx.x & 31;
    float part = 0.0f;
    #pragma unroll
    for (int rr = 0; rr < 4; rr++) {
        int r = wid * 4 + rr;
        float l0 = lgs[r][lane];
        float l1 = lgs[r][lane + 32];
        float l2 = (lane + 64 < VV) ? lgs[r][lane + 64] : -1e30f;
        float m = fmaxf(fmaxf(l0, l1), l2);
        #pragma unroll
        for (int off = 16; off; off >>= 1)
            m = fmaxf(m, __shfl_xor_sync(0xffffffffu, m, off));
        float sum = expf(l0 - m) + expf(l1 - m) +
                    ((lane + 64 < VV) ? expf(l2 - m) : 0.0f);
        #pragma unroll
        for (int off = 16; off; off >>= 1)
            sum += __shfl_xor_sync(0xffffffffu, sum, off);
        if (lane == 0)
            part += (m + logf(sum)) - lgs[r][tgt[r0 + r]];
    }
    if (lane == 0) atomicAdd(&g_loss, part);
}

// ---------------- output assembly -------------------------------------------
__global__ void __launch_bounds__(256) copy_out_kernel(
    const float* __restrict__ lg, float* __restrict__ out, int n)
{
    int i = blockIdx.x * 256 + threadIdx.x;
    if (i < n) out[i] = lg[i];
}
__global__ void __launch_bounds__(128) write_loss_kernel(
    float* __restrict__ out, int lo, int hi)
{
    int i = lo + blockIdx.x * 128 + threadIdx.x;
    if (i < hi) out[i] = g_loss * (1.0f / (float)MM);
}

// ---------------- launcher ----------------------------------------------------
extern "C" void kernel_launch(void* const* d_in, const int* in_sizes, int n_in,
                              void* d_out, int out_size)
{
    const int*   ids  = (const int*)d_in[0];
    const int*   tgt  = (const int*)d_in[1];
    const float* tok  = (const float*)d_in[2];
    const float* pos  = (const float*)d_in[3];
    const float* Wq   = (const float*)d_in[4];
    const float* Wk   = (const float*)d_in[5];
    const float* Wv   = (const float*)d_in[6];
    const float* Wo   = (const float*)d_in[7];
    const float* bo   = (const float*)d_in[8];
    const float* W1   = (const float*)d_in[9];
    const float* b1   = (const float*)d_in[10];
    const float* W2   = (const float*)d_in[11];
    const float* b2   = (const float*)d_in[12];
    const float* ln1g = (const float*)d_in[13];
    const float* ln1b = (const float*)d_in[14];
    const float* ln2g = (const float*)d_in[15];
    const float* ln2b = (const float*)d_in[16];
    const float* lnfg = (const float*)d_in[17];
    const float* lnfb = (const float*)d_in[18];
    const float* Wu   = (const float*)d_in[19];
    const float* bu   = (const float*)d_in[20];
    float* out = (float*)d_out;

    float *x, *h, *lg;
    __half *qkv, *hA1, *oA, *hidA, *Wqkv, *WoT, *W1T, *W2T;
    cudaGetSymbolAddress((void**)&x,    g_x);
    cudaGetSymbolAddress((void**)&h,    g_h);
    cudaGetSymbolAddress((void**)&qkv,  g_qkv);
    cudaGetSymbolAddress((void**)&hA1,  g_hA1);
    cudaGetSymbolAddress((void**)&oA,   g_oA);
    cudaGetSymbolAddress((void**)&hidA, g_hidA);
    cudaGetSymbolAddress((void**)&lg,   g_logits);
    cudaGetSymbolAddress((void**)&Wqkv, g_Wqkv);
    cudaGetSymbolAddress((void**)&WoT,  g_WoT);
    cudaGetSymbolAddress((void**)&W1T,  g_W1T);
    cudaGetSymbolAddress((void**)&W2T,  g_W2T);

    cudaFuncSetAttribute(gemm_mma<0>, cudaFuncAttributeMaxDynamicSharedMemorySize, GSMEM);
    cudaFuncSetAttribute(gemm_mma<1>, cudaFuncAttributeMaxDynamicSharedMemorySize, GSMEM);
    cudaFuncSetAttribute(gemm_mma<2>, cudaFuncAttributeMaxDynamicSharedMemorySize, GSMEM);

    int nlog = MM * VV;
    float* logits_dst = (out_size >= nlog) ? out : lg;

    // ---- weight prep: 2 launches ----
    dim3 pb(32, 8);
    prep_w_qkvo<<<dim3(DD/32, DD/32, 4*LL), pb>>>(Wq, Wk, Wv, Wo, Wqkv, WoT);
    prep_w_mlp<<<dim3(64, 16, 2*LL), pb>>>(W1, W2, W1T, W2T);

    embed_kernel<<<(MM * DD / 4) / 256, 256>>>(ids, tok, pos, x);

    for (int l = 0; l < LL; l++) {
        ln_single_kernel<<<MM / 8, 256>>>(x, ln1g + l * DD, ln1b + l * DD, hA1);

        // qkv(fp16) = hA1 @ Wqkv^T   K=512
        gemm_mma<0><<<dim3(KQKV/128, MM/128), 128, GSMEM>>>(
            hA1, DD, Wqkv + (size_t)l*KQKV*DD, DD, DD,
            nullptr, qkv, KQKV, nullptr, nullptr);

        attn_mma_kernel<<<BB * HH, 128>>>(qkv, oA);

        // x = x + o @ Wo + bo    K=512
        gemm_mma<1><<<dim3(DD/128, MM/128), 128, GSMEM>>>(
            oA, DD, WoT + (size_t)l*DD*DD, DD, DD,
            x, nullptr, DD, bo + l * DD, x);

        ln_single_kernel<<<MM / 8, 256>>>(x, ln2g + l * DD, ln2b + l * DD, hA1);

        // hidA(fp16) = gelu(hA1 @ W1^T + b1)   K=512
        gemm_mma<2><<<dim3(DFF/128, MM/128), 128, GSMEM>>>(
            hA1, DD, W1T + (size_t)l*DFF*DD, DD, DD,
            nullptr, hidA, DFF, b1 + l * DFF, nullptr);

        // x = x + hid @ W2 + b2   K=2048
        gemm_mma<1><<<dim3(DD/128, MM/128), 128, GSMEM>>>(
            hidA, DFF, W2T + (size_t)l*DD*DFF, DFF, DFF,
            x, nullptr, DD, b2 + l * DD, x);
    }

    ln_kernel<<<MM / 8, 256>>>(x, lnfg, lnfb, h);
    unembed_loss_kernel<<<MM / UROWS, 128>>>(h, Wu, bu, tgt, logits_dst);

    if (logits_dst != out) {
        int ncopy = out_size < nlog ? out_size : nlog;
        if (ncopy > 0)
            copy_out_kernel<<<(ncopy + 255) / 256, 256>>>(lg, out, ncopy);
    }
    if (out_size > nlog) {
        int tail = out_size - nlog;
        write_loss_kernel<<<(tail + 127) / 128, 128>>>(out, nlog, out_size);
    }
}